// round 11
// baseline (speedup 1.0000x reference)
#include <cuda_runtime.h>
#include <math.h>

#define NB     2048
#define KOBJ   8
#define H1     250
#define ROWS   (NB*KOBJ)       // 16384

__device__ float g_s1 [ROWS*H1];
__device__ float g_P  [ROWS*H1];
__device__ float g_Q  [ROWS*H1];
__device__ float g_eff[ROWS*H1];

typedef unsigned long long u64;

__device__ __forceinline__ float warp_sum(float v) {
#pragma unroll
    for (int o = 16; o; o >>= 1) v += __shfl_xor_sync(0xffffffffu, v, o);
    return v;
}
__device__ __forceinline__ void ffma2(u64& d, u64 a, u64 b) {
    asm("fma.rn.f32x2 %0, %1, %2, %0;" : "+l"(d) : "l"(a), "l"(b));
}
__device__ __forceinline__ u64 dup2(float x) {
    u64 r;
    asm("mov.b64 %0, {%1, %1};" : "=l"(r) : "r"(__float_as_uint(x)));
    return r;
}
__device__ __forceinline__ float2 unpk(u64 v) {
    float2 f;
    asm("mov.b64 {%0, %1}, %2;" : "=f"(f.x), "=f"(f.y) : "l"(v));
    return f;
}
__device__ __forceinline__ float fsel(float4 v, int m) {
    return (m == 0) ? v.x : (m == 1) ? v.y : (m == 2) ? v.z : v.w;
}
__device__ __forceinline__ void cp8(void* s, const void* g) {
    asm volatile("cp.async.ca.shared.global [%0], [%1], 8;"
                 :: "r"((unsigned)__cvta_generic_to_shared(s)), "l"(g));
}
__device__ __forceinline__ void cp4(void* s, const void* g) {
    asm volatile("cp.async.ca.shared.global [%0], [%1], 4;"
                 :: "r"((unsigned)__cvta_generic_to_shared(s)), "l"(g));
}
#define CP_COMMIT() asm volatile("cp.async.commit_group;")
#define CP_WAIT1()  asm volatile("cp.async.wait_group 1;")

__device__ __forceinline__ int colmap(int tx, int cc) {
    return (cc < 4) ? (tx * 4 + cc) : (128 + tx * 4 + (cc - 4));
}

// tf32 helpers
__device__ __forceinline__ float tf32c(float x) {
    unsigned r;
    asm("cvt.rna.tf32.f32 %0, %1;" : "=r"(r) : "f"(x));
    return __uint_as_float(r);
}
__device__ __forceinline__ void mma8(float* d, unsigned a0, unsigned a1,
                                     unsigned a2, unsigned a3,
                                     unsigned b0, unsigned b1) {
    asm volatile(
        "mma.sync.aligned.m16n8k8.row.col.f32.tf32.tf32.f32 "
        "{%0,%1,%2,%3},{%4,%5,%6,%7},{%8,%9},{%0,%1,%2,%3};"
        : "+f"(d[0]), "+f"(d[1]), "+f"(d[2]), "+f"(d[3])
        : "r"(a0), "r"(a1), "r"(a2), "r"(a3), "r"(b0), "r"(b1));
}

// ---------------------------------------------------------------------------
// fp32 FFMA2 SGEMM (enc only): BM=64, BN=256, BK=16; cp.async dbl-buffered.
// EPI==1: +bias, relu, LayerNorm.
// ---------------------------------------------------------------------------
template <int EPI>
__global__ __launch_bounds__(256, 2)
void gemm_kernel(const float* __restrict__ A, const float* __restrict__ W,
                 const float* __restrict__ bias, const float* __restrict__ g,
                 const float* __restrict__ bt, float* __restrict__ C,
                 int M, int K, int N)
{
    __shared__ float sA[2][64 * 20];
    __shared__ float sW[2][16 * 256];
    const int tid = threadIdx.x;
    const int tx = tid & 31, ty = tid >> 5;
    const int row0 = blockIdx.x * 64;
    const int NT = (K + 15) >> 4;

    auto issue = [&](int t, int buf) {
        int kt = t * 16;
#pragma unroll
        for (int c = 0; c < 2; ++c) {
            int q = tid + c * 256;
            int r = q >> 3, kk0 = (q & 7) * 2;
            int k = kt + kk0;
            float* d = &sA[buf][r * 20 + kk0];
            if (k + 2 <= K)     cp8(d, &A[(size_t)(row0 + r) * K + k]);
            else if (k < K) { cp4(d, &A[(size_t)(row0 + r) * K + k]); d[1] = 0.f; }
            else *(float2*)d = make_float2(0.f, 0.f);
        }
#pragma unroll
        for (int c = 0; c < 8; ++c) {
            int q = tid + c * 256;
            int kk = q >> 7, n0 = (q & 127) * 2;
            int k = kt + kk;
            float* d = &sW[buf][kk * 256 + n0];
            if (k < K && n0 + 2 <= N)   cp8(d, &W[(size_t)k * N + n0]);
            else if (k < K && n0 < N) { cp4(d, &W[(size_t)k * N + n0]); d[1] = 0.f; }
            else *(float2*)d = make_float2(0.f, 0.f);
        }
    };

    u64 acc2[8][4];
#pragma unroll
    for (int r = 0; r < 8; ++r)
#pragma unroll
        for (int p = 0; p < 4; ++p) acc2[r][p] = 0ull;

    issue(0, 0); CP_COMMIT();
    for (int t = 0; t < NT; ++t) {
        if (t + 1 < NT) issue(t + 1, (t + 1) & 1);
        CP_COMMIT();
        CP_WAIT1();
        __syncthreads();
        const float* aT = sA[t & 1];
        const float* wT = sW[t & 1];
#pragma unroll
        for (int k4 = 0; k4 < 4; ++k4) {
            float4 a4[8];
#pragma unroll
            for (int rr = 0; rr < 8; ++rr)
                a4[rr] = *(const float4*)&aT[(ty * 8 + rr) * 20 + k4 * 4];
#pragma unroll
            for (int m = 0; m < 4; ++m) {
                int kk = k4 * 4 + m;
                ulonglong2 wv0 = *(const ulonglong2*)&wT[kk * 256 + tx * 4];
                ulonglong2 wv1 = *(const ulonglong2*)&wT[kk * 256 + 128 + tx * 4];
                u64 w2[4] = {wv0.x, wv0.y, wv1.x, wv1.y};
#pragma unroll
                for (int rr = 0; rr < 8; ++rr) {
                    u64 ad = dup2(fsel(a4[rr], m));
#pragma unroll
                    for (int p = 0; p < 4; ++p) ffma2(acc2[rr][p], ad, w2[p]);
                }
            }
        }
        __syncthreads();
    }

    float invN = 1.f / (float)N;
#pragma unroll
    for (int rr = 0; rr < 8; ++rr) {
        int row = row0 + ty * 8 + rr;
        float v[8]; float s = 0.f;
#pragma unroll
        for (int cc = 0; cc < 8; ++cc) {
            float2 f = unpk(acc2[rr][cc >> 1]);
            float raw = (cc & 1) ? f.y : f.x;
            int n = colmap(tx, cc);
            float t = 0.f;
            if (n < N) t = fmaxf(raw + bias[n], 0.f);
            v[cc] = t; s += t;
        }
        s = warp_sum(s);
        float mu = s * invN;
        float q = 0.f;
#pragma unroll
        for (int cc = 0; cc < 8; ++cc) {
            int n = colmap(tx, cc);
            if (n < N) { float d = v[cc] - mu; q += d * d; }
        }
        q = warp_sum(q);
        float rs = rsqrtf(q * invN + 1e-5f);
#pragma unroll
        for (int cc = 0; cc < 8; ++cc) {
            int n = colmap(tx, cc);
            if (n < N) C[(size_t)row * N + n] = (v[cc] - mu) * rs * g[n] + bt[n];
        }
    }
}

// ---------------------------------------------------------------------------
// tf32 tensor-core GEMM: C = A[M,K] @ W[K,N] (N<=256). Block 64x256,
// 8 warps: wr=wid&3 (16 rows), wc=wid>>2 (128-col half). BK=16.
// Tiles staged in FRAGMENT-LINEAR smem order so compute is 1 LDS.64/fragment.
// m16n8k8 lane map (PTX): g=lane>>2, t=lane&3.
//   A: a0=(g,t) a1=(g+8,t) a2=(g,t+4) a3=(g+8,t+4)
//   B: b0=(k=t,n=g) b1=(k=t+4,n=g)
//   D: c0=(g,2t) c1=(g,2t+1) c2=(g+8,2t) c3=(g+8,2t+1)
// ---------------------------------------------------------------------------
__global__ __launch_bounds__(256, 2)
void gemm_tc(const float* __restrict__ A, const float* __restrict__ W,
             float* __restrict__ C, int M, int K, int N)
{
    __shared__ __align__(16) float sA[2 * 4 * 2 * 128];   // [buf][wr][q8][128]
    __shared__ __align__(16) float sW[2 * 2 * 32 * 64];   // [buf][q8][nt][64]
    const int tid = threadIdx.x;
    const int lane = tid & 31, wid = tid >> 5;
    const int wr = wid & 3, wc = wid >> 2;
    const int row0 = blockIdx.x * 64;
    const int NT = (K + 15) >> 4;

    // loader mapping
    const int ar = tid >> 2, akb = (tid & 3) * 4;      // A: row, k-base (4 elems)
    const int wkr = tid >> 4, wnb = (tid & 15) * 16;   // W: k-row, n-base (16 elems)

    float aR[4], wR[16];
    auto ldA = [&](int t) {
        int kt = t * 16;
#pragma unroll
        for (int e = 0; e < 4; e += 2) {
            int kg = kt + akb + e;
            if (kg + 2 <= K) {
                float2 v = *(const float2*)&A[(size_t)(row0 + ar) * K + kg];
                aR[e] = tf32c(v.x); aR[e + 1] = tf32c(v.y);
            } else {
                aR[e]     = (kg     < K) ? tf32c(A[(size_t)(row0 + ar) * K + kg])     : 0.f;
                aR[e + 1] = (kg + 1 < K) ? tf32c(A[(size_t)(row0 + ar) * K + kg + 1]) : 0.f;
            }
        }
    };
    auto ldW = [&](int t) {
        int kg = t * 16 + wkr;
#pragma unroll
        for (int e = 0; e < 16; e += 2) {
            int n = wnb + e;
            if (kg < K && n + 2 <= N) {
                float2 v = *(const float2*)&W[(size_t)kg * N + n];
                wR[e] = tf32c(v.x); wR[e + 1] = tf32c(v.y);
            } else {
                wR[e]     = (kg < K && n     < N) ? tf32c(W[(size_t)kg * N + n])     : 0.f;
                wR[e + 1] = (kg < K && n + 1 < N) ? tf32c(W[(size_t)kg * N + n + 1]) : 0.f;
            }
        }
    };
    auto stA = [&](int buf) {
        int g = ar & 7, h = (ar >> 3) & 1, wri = ar >> 4;
#pragma unroll
        for (int e = 0; e < 4; ++e) {
            int kl = akb + e;
            int q8 = kl >> 3, kk = kl & 7, t = kk & 3, qq = kk >> 2;
            sA[((buf * 4 + wri) * 2 + q8) * 128 + qq * 64 + (g * 4 + t) * 2 + h] = aR[e];
        }
    };
    auto stW = [&](int buf) {
        int q8 = wkr >> 3, kk = wkr & 7, t = kk & 3, h = kk >> 2;
#pragma unroll
        for (int e = 0; e < 16; ++e) {
            int n = wnb + e;
            int nt = n >> 3, gg = n & 7;
            sW[((buf * 2 + q8) * 32 + nt) * 64 + (gg * 4 + t) * 2 + h] = wR[e];
        }
    };

    float accd[16][4];
#pragma unroll
    for (int i = 0; i < 16; ++i)
#pragma unroll
        for (int j = 0; j < 4; ++j) accd[i][j] = 0.f;

    ldA(0); ldW(0); stA(0); stW(0);
    __syncthreads();
    for (int t = 0; t < NT; ++t) {
        if (t + 1 < NT) { ldA(t + 1); ldW(t + 1); }
        int buf = t & 1;
#pragma unroll
        for (int q8 = 0; q8 < 2; ++q8) {
            const float* aB = &sA[((buf * 4 + wr) * 2 + q8) * 128];
            uint2 a01 = *(const uint2*)&aB[2 * lane];
            uint2 a23 = *(const uint2*)&aB[64 + 2 * lane];
#pragma unroll
            for (int nt = 0; nt < 16; ++nt) {
                uint2 b = *(const uint2*)
                    &sW[((buf * 2 + q8) * 32 + wc * 16 + nt) * 64 + 2 * lane];
                mma8(accd[nt], a01.x, a01.y, a23.x, a23.y, b.x, b.y);
            }
        }
        if (t + 1 < NT) { stA((t + 1) & 1); stW((t + 1) & 1); }
        __syncthreads();
    }

    // store: lane holds rows (g, g+8), cols (2t, 2t+1) per n8 tile
    const int g = lane >> 2, t4 = lane & 3;
    int rowA = row0 + wr * 16 + g;
    int rowB = rowA + 8;
#pragma unroll
    for (int nt = 0; nt < 16; ++nt) {
        int n = wc * 128 + nt * 8 + 2 * t4;
        if (n + 2 <= N) {
            *(float2*)&C[(size_t)rowA * N + n] = make_float2(accd[nt][0], accd[nt][1]);
            *(float2*)&C[(size_t)rowB * N + n] = make_float2(accd[nt][2], accd[nt][3]);
        } else if (n < N) {
            C[(size_t)rowA * N + n] = accd[nt][0];
            C[(size_t)rowB * N + n] = accd[nt][2];
        }
    }
}

// ---------------------------------------------------------------------------
// tf32 tensor-core OUT GEMM: [s1|effect|x] @ out_W + out_b. K=1076, N=250.
// Same structure as gemm_tc; A gathered element-wise from 3 sources.
// ---------------------------------------------------------------------------
__global__ __launch_bounds__(256, 2)
void out_gemm_tc(const float* __restrict__ s1, const float* __restrict__ eff,
                 const float* __restrict__ x, const float* __restrict__ W,
                 const float* __restrict__ bias, float* __restrict__ C)
{
    const int K = 1076, N = 250;
    __shared__ __align__(16) float sA[2 * 4 * 2 * 128];
    __shared__ __align__(16) float sW[2 * 2 * 32 * 64];
    const int tid = threadIdx.x;
    const int lane = tid & 31, wid = tid >> 5;
    const int wr = wid & 3, wc = wid >> 2;
    const int row0 = blockIdx.x * 64;
    const int NT = (K + 15) >> 4;   // 68

    const int ar = tid >> 2, akb = (tid & 3) * 4;
    const int wkr = tid >> 4, wnb = (tid & 15) * 16;

    float aR[4], wR[16];
    auto ldA = [&](int t) {
        int kt = t * 16;
        size_t row = row0 + ar;
#pragma unroll
        for (int e = 0; e < 4; ++e) {
            int k = kt + akb + e;
            float v = 0.f;
            if (k < 250)       v = s1 [row * 250 + k];
            else if (k < 500)  v = eff[row * 250 + (k - 250)];
            else if (k < 1076) v = x  [row * 576 + (k - 500)];
            aR[e] = tf32c(v);
        }
    };
    auto ldW = [&](int t) {
        int kg = t * 16 + wkr;
#pragma unroll
        for (int e = 0; e < 16; e += 2) {
            int n = wnb + e;
            if (kg < K && n + 2 <= N) {
                float2 v = *(const float2*)&W[(size_t)kg * N + n];
                wR[e] = tf32c(v.x); wR[e + 1] = tf32c(v.y);
            } else {
                wR[e]     = (kg < K && n     < N) ? tf32c(W[(size_t)kg * N + n])     : 0.f;
                wR[e + 1] = (kg < K && n + 1 < N) ? tf32c(W[(size_t)kg * N + n + 1]) : 0.f;
            }
        }
    };
    auto stA = [&](int buf) {
        int g = ar & 7, h = (ar >> 3) & 1, wri = ar >> 4;
#pragma unroll
        for (int e = 0; e < 4; ++e) {
            int kl = akb + e;
            int q8 = kl >> 3, kk = kl & 7, t = kk & 3, qq = kk >> 2;
            sA[((buf * 4 + wri) * 2 + q8) * 128 + qq * 64 + (g * 4 + t) * 2 + h] = aR[e];
        }
    };
    auto stW = [&](int buf) {
        int q8 = wkr >> 3, kk = wkr & 7, t = kk & 3, h = kk >> 2;
#pragma unroll
        for (int e = 0; e < 16; ++e) {
            int n = wnb + e;
            int nt = n >> 3, gg = n & 7;
            sW[((buf * 2 + q8) * 32 + nt) * 64 + (gg * 4 + t) * 2 + h] = wR[e];
        }
    };

    float accd[16][4];
#pragma unroll
    for (int i = 0; i < 16; ++i)
#pragma unroll
        for (int j = 0; j < 4; ++j) accd[i][j] = 0.f;

    ldA(0); ldW(0); stA(0); stW(0);
    __syncthreads();
    for (int t = 0; t < NT; ++t) {
        if (t + 1 < NT) { ldA(t + 1); ldW(t + 1); }
        int buf = t & 1;
#pragma unroll
        for (int q8 = 0; q8 < 2; ++q8) {
            const float* aB = &sA[((buf * 4 + wr) * 2 + q8) * 128];
            uint2 a01 = *(const uint2*)&aB[2 * lane];
            uint2 a23 = *(const uint2*)&aB[64 + 2 * lane];
#pragma unroll
            for (int nt = 0; nt < 16; ++nt) {
                uint2 b = *(const uint2*)
                    &sW[((buf * 2 + q8) * 32 + wc * 16 + nt) * 64 + 2 * lane];
                mma8(accd[nt], a01.x, a01.y, a23.x, a23.y, b.x, b.y);
            }
        }
        if (t + 1 < NT) { stA((t + 1) & 1); stW((t + 1) & 1); }
        __syncthreads();
    }

    const int g = lane >> 2, t4 = lane & 3;
    int rowA = row0 + wr * 16 + g;
    int rowB = rowA + 8;
#pragma unroll
    for (int nt = 0; nt < 16; ++nt) {
        int n = wc * 128 + nt * 8 + 2 * t4;
        if (n + 2 <= N) {
            *(float2*)&C[(size_t)rowA * N + n] =
                make_float2(accd[nt][0] + bias[n], accd[nt][1] + bias[n + 1]);
            *(float2*)&C[(size_t)rowB * N + n] =
                make_float2(accd[nt][2] + bias[n], accd[nt][3] + bias[n + 1]);
        } else if (n < N) {
            C[(size_t)rowA * N + n] = accd[nt][0] + bias[n];
            C[(size_t)rowB * N + n] = accd[nt][2] + bias[n];
        }
    }
}

// ---------------------------------------------------------------------------
// Fused pair kernel (R10-best, unchanged): 512 threads, 2 b-groups/block.
// ---------------------------------------------------------------------------
#define PSC    0
#define PUN    (112 * 256)              /* 28672 */
#define P_SATT (PUN + 24576)            /* 53248 */
#define P_TOT  (P_SATT + 128)           /* 53376 floats */

__global__ __launch_bounds__(512, 1)
void pair_kernel(const float* __restrict__ P, const float* __restrict__ Q,
                 const float* __restrict__ core_b, const float* __restrict__ core_g,
                 const float* __restrict__ core_bt,
                 const float* __restrict__ ctxW, const float* __restrict__ ctx_b,
                 const float* __restrict__ ctx_g, const float* __restrict__ ctx_bt,
                 const float* __restrict__ attW1, const float* __restrict__ att_b1,
                 const float* __restrict__ att_g, const float* __restrict__ att_bt,
                 const float* __restrict__ attW2, const float* __restrict__ att_b2,
                 float* __restrict__ effect)
{
    extern __shared__ float sm[];
    float* sC   = sm + PSC;
    float* sP   = sm + PUN;
    float* sQ   = sm + PUN + 4000;
    float* sAtt = sm + P_SATT;

    const int tid = threadIdx.x;
    const int tx = tid & 31, wy = tid >> 5;
    const int b0 = blockIdx.x * 2;

    auto issue_att = [&](int t, int buf) {
        int kt0 = t * 32;
        float* dst = sm + PUN + 16384 + buf * 4096;
#pragma unroll
        for (int c = 0; c < 4; ++c) {
            int q = tid + c * 512;
            int kk = q >> 6, n = (q & 63) * 2;
            int k = kt0 + kk;
            float* d = &dst[kk * 128 + n];
            if (k < 250 && n + 2 <= 100) cp8(d, &attW1[(size_t)k * 100 + n]);
            else *(float2*)d = make_float2(0.f, 0.f);
        }
    };
    auto issue_ctx = [&](int t, int buf) {
        int kt0 = t * 32;
        float* dst = sm + PUN + buf * 8192;
#pragma unroll
        for (int c = 0; c < 8; ++c) {
            int q = tid + c * 512;
            int kk = q >> 7, n = (q & 127) * 2;
            int k = kt0 + kk;
            float* d = &dst[kk * 256 + n];
            if (k < 250 && n + 2 <= 250) cp8(d, &ctxW[(size_t)k * 250 + n]);
            else *(float2*)d = make_float2(0.f, 0.f);
        }
    };

    issue_att(0, 0); CP_COMMIT();

#pragma unroll
    for (int c = 0; c < 2; ++c) {
        int idx = tid + c * 512;
        if (idx < 1000) {
            *(float4*)&sP[idx * 4] = *(const float4*)&P[(size_t)b0 * 2000 + idx * 4];
            *(float4*)&sQ[idx * 4] = *(const float4*)&Q[(size_t)b0 * 2000 + idx * 4];
        }
    }
    __syncthreads();

    for (int l = wy; l < 112; l += 16) {
        int bi = l / 56, pr = l % 56;
        int i = pr / 7, jj = pr % 7;
        int j = jj + (jj >= i ? 1 : 0);
        const float* Pr = &sP[(bi * 8 + i) * 250];
        const float* Qr = &sQ[(bi * 8 + j) * 250];
        float v[8]; float s = 0.f;
#pragma unroll
        for (int t = 0; t < 8; ++t) {
            int c = tx + 32 * t;
            float val = 0.f;
            if (c < 250) val = fmaxf(Pr[c] + Qr[c] + core_b[c], 0.f);
            v[t] = val; s += val;
        }
        s = warp_sum(s);
        float mu = s * (1.f / 250.f);
        float q = 0.f;
#pragma unroll
        for (int t = 0; t < 8; ++t) {
            int c = tx + 32 * t;
            if (c < 250) { float d = v[t] - mu; q += d * d; }
        }
        q = warp_sum(q);
        float rs = rsqrtf(q * (1.f / 250.f) + 1e-5f);
#pragma unroll
        for (int t = 0; t < 8; ++t) {
            int c = tx + 32 * t;
            if (c < 250) sC[l * 256 + c] = (v[t] - mu) * rs * core_g[c] + core_bt[c];
            else         sC[l * 256 + c] = 0.f;
        }
    }
    __syncthreads();

    u64 accA2[7][2];
#pragma unroll
    for (int r = 0; r < 7; ++r) { accA2[r][0] = 0ull; accA2[r][1] = 0ull; }

    for (int t = 0; t < 8; ++t) {
        if (t < 7) issue_att(t + 1, (t + 1) & 1);
        CP_COMMIT();
        CP_WAIT1();
        __syncthreads();
        const float* wT = sm + PUN + 16384 + (t & 1) * 4096;
        int kt0 = t * 32;
#pragma unroll
        for (int k4 = 0; k4 < 8; ++k4) {
            float4 a4[7];
#pragma unroll
            for (int rr = 0; rr < 7; ++rr)
                a4[rr] = *(const float4*)&sC[(wy * 7 + rr) * 256 + kt0 + k4 * 4];
#pragma unroll
            for (int m = 0; m < 4; ++m) {
                int kk = k4 * 4 + m;
                ulonglong2 wa = *(const ulonglong2*)&wT[kk * 128 + tx * 4];
#pragma unroll
                for (int rr = 0; rr < 7; ++rr) {
                    u64 ad = dup2(fsel(a4[rr], m));
                    ffma2(accA2[rr][0], ad, wa.x);
                    ffma2(accA2[rr][1], ad, wa.y);
                }
            }
        }
        __syncthreads();
    }

    issue_ctx(0, 0); CP_COMMIT();

#pragma unroll
    for (int rr = 0; rr < 7; ++rr) {
        int row = wy * 7 + rr;
        float h[4]; float s = 0.f;
#pragma unroll
        for (int cc = 0; cc < 4; ++cc) {
            float2 f = unpk(accA2[rr][cc >> 1]);
            float raw = (cc & 1) ? f.y : f.x;
            int c = tx * 4 + cc;
            float t = 0.f;
            if (c < 100) t = tanhf(raw + att_b1[c]);
            h[cc] = t; s += t;
        }
        s = warp_sum(s);
        float mu = s * (1.f / 100.f);
        float q = 0.f;
#pragma unroll
        for (int cc = 0; cc < 4; ++cc) {
            int c = tx * 4 + cc;
            if (c < 100) { float d = h[cc] - mu; q += d * d; }
        }
        q = warp_sum(q);
        float rs = rsqrtf(q * (1.f / 100.f) + 1e-5f);
        float p = 0.f;
#pragma unroll
        for (int cc = 0; cc < 4; ++cc) {
            int c = tx * 4 + cc;
            if (c < 100) p += ((h[cc] - mu) * rs * att_g[c] + att_bt[c]) * attW2[c];
        }
        p = warp_sum(p);
        if (tx == 0) sAtt[row] = 1.f / (1.f + expf(-(p + att_b2[0])));
    }
    __syncthreads();

    u64 accC2[7][4];
#pragma unroll
    for (int r = 0; r < 7; ++r)
#pragma unroll
        for (int p = 0; p < 4; ++p) accC2[r][p] = 0ull;

    for (int t = 0; t < 8; ++t) {
        if (t < 7) issue_ctx(t + 1, (t + 1) & 1);
        CP_COMMIT();
        CP_WAIT1();
        __syncthreads();
        const float* wT = sm + PUN + (t & 1) * 8192;
        int kt0 = t * 32;
#pragma unroll
        for (int k4 = 0; k4 < 8; ++k4) {
            float4 a4[7];
#pragma unroll
            for (int rr = 0; rr < 7; ++rr)
                a4[rr] = *(const float4*)&sC[(wy * 7 + rr) * 256 + kt0 + k4 * 4];
#pragma unroll
            for (int m = 0; m < 4; ++m) {
                int kk = k4 * 4 + m;
                ulonglong2 wv0 = *(const ulonglong2*)&wT[kk * 256 + tx * 4];
                ulonglong2 wv1 = *(const ulonglong2*)&wT[kk * 256 + 128 + tx * 4];
                u64 w2[4] = {wv0.x, wv0.y, wv1.x, wv1.y};
#pragma unroll
                for (int rr = 0; rr < 7; ++rr) {
                    u64 ad = dup2(fsel(a4[rr], m));
#pragma unroll
                    for (int p = 0; p < 4; ++p) ffma2(accC2[rr][p], ad, w2[p]);
                }
            }
        }
        __syncthreads();
    }

    const int bi = wy >> 3, ig = wy & 7;
    float eff[8];
#pragma unroll
    for (int cc = 0; cc < 8; ++cc) eff[cc] = 0.f;
#pragma unroll
    for (int rr = 0; rr < 7; ++rr) {
        int row = wy * 7 + rr;
        float v[8]; float s = 0.f;
#pragma unroll
        for (int cc = 0; cc < 8; ++cc) {
            float2 f = unpk(accC2[rr][cc >> 1]);
            float raw = (cc & 1) ? f.y : f.x;
            int c = colmap(tx, cc);
            float t = 0.f;
            if (c < 250) t = fmaxf(raw + ctx_b[c], 0.f);
            v[cc] = t; s += t;
        }
        s = warp_sum(s);
        float mu = s * (1.f / 250.f);
        float q = 0.f;
#pragma unroll
        for (int cc = 0; cc < 8; ++cc) {
            int c = colmap(tx, cc);
            if (c < 250) { float d = v[cc] - mu; q += d * d; }
        }
        q = warp_sum(q);
        float rs = rsqrtf(q * (1.f / 250.f) + 1e-5f);
        float aw = sAtt[row];
#pragma unroll
        for (int cc = 0; cc < 8; ++cc) {
            int c = colmap(tx, cc);
            if (c < 250) eff[cc] += ((v[cc] - mu) * rs * ctx_g[c] + ctx_bt[c]) * aw;
        }
    }
#pragma unroll
    for (int cc = 0; cc < 8; ++cc) {
        int c = colmap(tx, cc);
        if (c < 250) effect[((size_t)(b0 + bi) * 8 + ig) * 250 + c] = eff[cc];
    }
}

// ---------------------------------------------------------------------------
extern "C" void kernel_launch(void* const* d_in, const int* in_sizes, int n_in,
                              void* d_out, int out_size)
{
    const float* x      = (const float*)d_in[0];
    const float* state  = (const float*)d_in[1];
    const float* enc_W  = (const float*)d_in[2];
    const float* enc_b  = (const float*)d_in[3];
    const float* enc_g  = (const float*)d_in[4];
    const float* enc_bt = (const float*)d_in[5];
    const float* core_W = (const float*)d_in[6];
    const float* core_b = (const float*)d_in[7];
    const float* core_g = (const float*)d_in[8];
    const float* core_bt= (const float*)d_in[9];
    const float* ctx_W  = (const float*)d_in[10];
    const float* ctx_b  = (const float*)d_in[11];
    const float* ctx_g  = (const float*)d_in[12];
    const float* ctx_bt = (const float*)d_in[13];
    const float* att_W1 = (const float*)d_in[14];
    const float* att_b1 = (const float*)d_in[15];
    const float* att_g  = (const float*)d_in[16];
    const float* att_bt = (const float*)d_in[17];
    const float* att_W2 = (const float*)d_in[18];
    const float* att_b2 = (const float*)d_in[19];
    const float* out_W  = (const float*)d_in[20];
    const float* out_b  = (const float*)d_in[21];
    float* out = (float*)d_out;

    float *p_s1, *p_P, *p_Q, *p_eff;
    cudaGetSymbolAddress((void**)&p_s1,  g_s1);
    cudaGetSymbolAddress((void**)&p_P,   g_P);
    cudaGetSymbolAddress((void**)&p_Q,   g_Q);
    cudaGetSymbolAddress((void**)&p_eff, g_eff);

    cudaFuncSetAttribute(pair_kernel, cudaFuncAttributeMaxDynamicSharedMemorySize,
                         P_TOT * (int)sizeof(float));

    // 1) s1 = LN(relu(state @ enc_W + enc_b))  [fp32 FFMA2]
    gemm_kernel<1><<<ROWS / 64, 256>>>(state, enc_W, enc_b, enc_g, enc_bt,
                                       p_s1, ROWS, 250, 250);
    // 2) P = s1 @ core_W[:250], Q = s1 @ core_W[250:]  [tf32 tensor core]
    gemm_tc<<<ROWS / 64, 256>>>(p_s1, core_W,             p_P, ROWS, 250, 250);
    gemm_tc<<<ROWS / 64, 256>>>(p_s1, core_W + 250 * 250, p_Q, ROWS, 250, 250);
    // 3) fused pair/ctx/att/effect  [fp32 FFMA2]
    pair_kernel<<<NB / 2, 512, P_TOT * (int)sizeof(float)>>>(
        p_P, p_Q, core_b, core_g, core_bt,
        ctx_W, ctx_b, ctx_g, ctx_bt,
        att_W1, att_b1, att_g, att_bt,
        att_W2, att_b2, p_eff);
    // 4) new_state = [s1|effect|x] @ out_W + out_b  [tf32 tensor core]
    out_gemm_tc<<<ROWS / 64, 256>>>(p_s1, p_eff, x, out_W, out_b, out);
}